// round 4
// baseline (speedup 1.0000x reference)
#include <cuda_runtime.h>
#include <cstdint>

#define Bsz 128
#define Ssz 512
#define Hsz 1024
#define NL  4
#define NPART 6

// out layout: output [512,128,1024], state_h [4,128,1024], state_c [4,128,1024]
#define OUT_OFF_H ((size_t)512 * 128 * 1024)
#define OUT_OFF_C (OUT_OFF_H + (size_t)4 * 128 * 1024)

// ---------------- scratch (__device__ globals; no allocations allowed) ------
__device__ int   d_len[Bsz];
__device__ int   d_sorted[Bsz];
__device__ int   d_unsort[Bsz];
__device__ int   d_bslast;
__device__ float d_xtT[2][Hsz][Bsz];           // transposed activations [hc][r], sorted order
__device__ float d_hfin[Bsz][Hsz];             // final top-layer h, row-major [r][hc]
__device__ float d_G2[NPART][3 * Hsz][Bsz];    // split-K partials: [part][vm][r]

// ---------------- kernel 1: lengths[b] = count(x[b,:] > 0) ------------------
__global__ void k_lengths(const int* __restrict__ x) {
    int b = blockIdx.x;
    int t = threadIdx.x;
    int cnt = 0;
    for (int s = t; s < Ssz; s += blockDim.x) cnt += (x[b * Ssz + s] > 0);
    #pragma unroll
    for (int o = 16; o; o >>= 1) cnt += __shfl_down_sync(0xFFFFFFFFu, cnt, o);
    __shared__ int ws[8];
    if ((t & 31) == 0) ws[t >> 5] = cnt;
    __syncthreads();
    if (t == 0) {
        int s = 0;
        for (int w = 0; w < (int)blockDim.x / 32; w++) s += ws[w];
        d_len[b] = s;
    }
}

// ---------------- kernel 2: stable descending argsort (B=128, O(B^2)) -------
__global__ void k_sort() {
    __shared__ int sl[Bsz];
    int i = threadIdx.x;
    sl[i] = d_len[i];
    __syncthreads();
    int li = sl[i];
    int rank = 0, c512 = 0;
    #pragma unroll 8
    for (int j = 0; j < Bsz; j++) {
        int lj = sl[j];
        rank += (lj > li) || (lj == li && j < i);
        c512 += (lj >= Ssz);
    }
    d_unsort[i] = rank;
    d_sorted[rank] = i;
    if (i == 0) d_bslast = c512;
}

// ---------------- kernel 3: xt0T[hc][r] = emb[ x[sorted[r], 0] ][hc] --------
__global__ void k_gather(const int* __restrict__ x, const float* __restrict__ emb) {
    int r = blockIdx.x;
    int tok = x[d_sorted[r] * Ssz];  // t = 0
    #pragma unroll
    for (int j = 0; j < 4; j++) {
        int hc = threadIdx.x + j * 256;
        d_xtT[0][hc][r] = emb[(size_t)tok * Hsz + hc];
    }
}

// ---------------- kernel 4: 3xTF32 tensor-core GEMM -------------------------
// C[vm=3072 gate cols][r=128] = W_sel[vm][k] * xT[k][r], k = 1024, split-K 6.
// vm -> W row: vm<1024 -> vm (i), 1024..2047 -> vm+1024 (g), 2048..3071 -> vm+1024 (o)
#define AS_STRIDE 20    // 128 x 16 fp32 weight tile, pad to 20
#define BS_STRIDE 132   // 16 x 128 fp32 x tile [k][r], pad to 132

__device__ __forceinline__ unsigned f2tf(float f) {
    unsigned r; asm("cvt.rna.tf32.f32 %0, %1;" : "=r"(r) : "f"(f)); return r;
}
__device__ __forceinline__ void mma8(float* c, const unsigned* a, const unsigned* b) {
    asm volatile(
        "mma.sync.aligned.m16n8k8.row.col.f32.tf32.tf32.f32 "
        "{%0,%1,%2,%3}, {%4,%5,%6,%7}, {%8,%9}, {%0,%1,%2,%3};"
        : "+f"(c[0]), "+f"(c[1]), "+f"(c[2]), "+f"(c[3])
        : "r"(a[0]), "r"(a[1]), "r"(a[2]), "r"(a[3]), "r"(b[0]), "r"(b[1]));
}
__device__ __forceinline__ void cpa16(unsigned s, const float* g) {
    asm volatile("cp.async.cg.shared.global [%0], [%1], 16;" :: "r"(s), "l"(g));
}

__global__ void __launch_bounds__(256) k_gemm2(const float* __restrict__ W, int cur) {
    __shared__ __align__(16) float As[2][128 * AS_STRIDE];
    __shared__ __align__(16) float Bs[2][16 * BS_STRIDE];

    int tid  = threadIdx.x;
    int vm0  = blockIdx.x * 128;               // 0..2944
    int gate = vm0 >> 10;
    const float* A  = W + (size_t)(vm0 + (gate > 0 ? 1024 : 0)) * Hsz;
    const float* BT = &d_xtT[cur][0][0];

    int part = blockIdx.y;
    int i0 = part * 64 / NPART, i1 = (part + 1) * 64 / NPART;  // BK=16 stages
    int niter = i1 - i0;

    unsigned asb[2], bsb[2];
    asb[0] = (unsigned)__cvta_generic_to_shared(&As[0][0]);
    asb[1] = (unsigned)__cvta_generic_to_shared(&As[1][0]);
    bsb[0] = (unsigned)__cvta_generic_to_shared(&Bs[0][0]);
    bsb[1] = (unsigned)__cvta_generic_to_shared(&Bs[1][0]);

    // stage loader: A 128x16 (512 16B chunks) + B 16x128 (512 16B chunks) = 1024
    auto load_stage = [&](int buf, int iter) {
        int kw = iter * 16;
        #pragma unroll
        for (int e = 0; e < 4; e++) {
            int c = tid + e * 256;
            if (c < 512) {
                int row = c >> 2, seg = c & 3;            // A: 4 chunks/row of 16
                cpa16(asb[buf] + (unsigned)(row * AS_STRIDE + seg * 4) * 4,
                      A + (size_t)row * Hsz + kw + seg * 4);
            } else {
                int cb = c - 512;
                int kr = cb >> 5, seg = cb & 31;          // B: 32 chunks/row of 128
                cpa16(bsb[buf] + (unsigned)(kr * BS_STRIDE + seg * 4) * 4,
                      BT + (size_t)(kw + kr) * Bsz + seg * 4);
            }
        }
    };

    int lane = tid & 31, wid = tid >> 5;
    int wm = (wid & 3) * 32;      // warp m offset (gate cols)
    int wn = (wid >> 2) * 64;     // warp n offset (batch rows)
    int g  = lane >> 2, tg = lane & 3;

    float acc[2][8][4];
    #pragma unroll
    for (int a = 0; a < 2; a++)
        #pragma unroll
        for (int b = 0; b < 8; b++)
            #pragma unroll
            for (int cxx = 0; cxx < 4; cxx++) acc[a][b][cxx] = 0.f;

    load_stage(0, i0);
    asm volatile("cp.async.commit_group;" ::: "memory");

    for (int it = 0; it < niter; ++it) {
        if (it + 1 < niter) load_stage((it + 1) & 1, i0 + it + 1);
        asm volatile("cp.async.commit_group;" ::: "memory");
        asm volatile("cp.async.wait_group 1;" ::: "memory");
        __syncthreads();

        const float* As_ = &As[it & 1][0];
        const float* Bs_ = &Bs[it & 1][0];

        #pragma unroll
        for (int ks = 0; ks < 2; ks++) {
            int kb = ks * 8;
            unsigned bh[8][2], bl[8][2];
            #pragma unroll
            for (int nf = 0; nf < 8; nf++) {
                int n = wn + nf * 8 + g;
                float b0 = Bs_[(kb + tg) * BS_STRIDE + n];
                float b1 = Bs_[(kb + tg + 4) * BS_STRIDE + n];
                bh[nf][0] = f2tf(b0);
                bl[nf][0] = f2tf(b0 - __uint_as_float(bh[nf][0]));
                bh[nf][1] = f2tf(b1);
                bl[nf][1] = f2tf(b1 - __uint_as_float(bh[nf][1]));
            }
            #pragma unroll
            for (int mf = 0; mf < 2; mf++) {
                int row = wm + mf * 16 + g;
                float a0 = As_[row * AS_STRIDE + kb + tg];
                float a1 = As_[(row + 8) * AS_STRIDE + kb + tg];
                float a2 = As_[row * AS_STRIDE + kb + tg + 4];
                float a3 = As_[(row + 8) * AS_STRIDE + kb + tg + 4];
                unsigned ah[4] = {f2tf(a0), f2tf(a1), f2tf(a2), f2tf(a3)};
                unsigned al[4] = {f2tf(a0 - __uint_as_float(ah[0])),
                                  f2tf(a1 - __uint_as_float(ah[1])),
                                  f2tf(a2 - __uint_as_float(ah[2])),
                                  f2tf(a3 - __uint_as_float(ah[3]))};
                // Three runs of 8 INDEPENDENT MMAs each (different acc per issue)
                // instead of 3-deep same-acc RAW chains: keeps HMMA pipe fed.
                #pragma unroll
                for (int nf = 0; nf < 8; nf++) mma8(acc[mf][nf], ah, bh[nf]);
                #pragma unroll
                for (int nf = 0; nf < 8; nf++) mma8(acc[mf][nf], al, bh[nf]);
                #pragma unroll
                for (int nf = 0; nf < 8; nf++) mma8(acc[mf][nf], ah, bl[nf]);
            }
        }
        __syncthreads();
    }

    // epilogue: write split-K partials, [vm][r], float2 per fragment row
    float* Gp = &d_G2[part][0][0];
    #pragma unroll
    for (int mf = 0; mf < 2; mf++)
        #pragma unroll
        for (int nf = 0; nf < 8; nf++) {
            int m0 = vm0 + wm + mf * 16 + g;
            int n0 = wn + nf * 8 + tg * 2;
            float2 v01 = make_float2(acc[mf][nf][0], acc[mf][nf][1]);
            float2 v23 = make_float2(acc[mf][nf][2], acc[mf][nf][3]);
            *(float2*)(Gp + (size_t)m0 * Bsz + n0)       = v01;
            *(float2*)(Gp + (size_t)(m0 + 8) * Bsz + n0) = v23;
        }
}

// ---------------- kernel 5: split-K reduce + LSTM activations ---------------
__device__ __forceinline__ float sigmoidf_(float x) { return 1.0f / (1.0f + expf(-x)); }

__global__ void __launch_bounds__(256) k_act2(const float* __restrict__ bih,
                                              const float* __restrict__ bhh,
                                              int l, int nxt, float* __restrict__ out) {
    __shared__ float sh[16][129], sc[16][129];
    int tid = threadIdx.x;
    int hb = blockIdx.x * 16;       // grid = 64 blocks
    int bsl = d_bslast;

    #pragma unroll
    for (int w = 0; w < 8; w++) {
        int idx = w * 256 + tid;
        int hcl = idx >> 7, r = idx & 127;
        int hc = hb + hcl;
        float gi = 0.f, gg = 0.f, go = 0.f;
        #pragma unroll
        for (int p = 0; p < NPART; p++) {
            gi += d_G2[p][hc][r];
            gg += d_G2[p][Hsz + hc][r];
            go += d_G2[p][2 * Hsz + hc][r];
        }
        gi += bih[hc] + bhh[hc];
        gg += bih[2 * Hsz + hc] + bhh[2 * Hsz + hc];
        go += bih[3 * Hsz + hc] + bhh[3 * Hsz + hc];
        float cc = sigmoidf_(gi) * tanhf(gg);
        float hh = sigmoidf_(go) * tanhf(cc);
        d_xtT[nxt][hc][r] = hh;           // unmasked h feeds next layer
        sh[hcl][r] = hh;
        sc[hcl][r] = cc;
    }
    __syncthreads();
    #pragma unroll
    for (int w = 0; w < 8; w++) {
        int idx = w * 256 + tid;
        int r = idx >> 4, hcl = idx & 15;
        float m = (r < bsl) ? 1.f : 0.f;
        size_t o = ((size_t)(l * Bsz + r) << 10) + hb + hcl;
        float hh = sh[hcl][r];
        out[OUT_OFF_H + o] = hh * m;
        out[OUT_OFF_C + o] = sc[hcl][r] * m;
        d_hfin[r][hb + hcl] = hh;          // row-major final h (last layer wins)
    }
}

// ---------------- kernel 6: output[t,b,:] = (t < len[b]) * h_top[b,:] -------
__global__ void k_output(float* __restrict__ out) {
    int b  = blockIdx.x;
    int tb = blockIdx.y * 64;
    int len = d_len[b];
    int rk  = d_unsort[b];
    float4 hv = *(const float4*)&d_hfin[rk][threadIdx.x * 4];
    float4 z  = make_float4(0.f, 0.f, 0.f, 0.f);
    size_t col = (size_t)threadIdx.x * 4;
    #pragma unroll 4
    for (int t = tb; t < tb + 64; t++) {
        float4 v = (t < len) ? hv : z;
        *(float4*)&out[(((size_t)t * Bsz) + b) * Hsz + col] = v;
    }
}

// ---------------- launch -----------------------------------------------------
extern "C" void kernel_launch(void* const* d_in, const int* in_sizes, int n_in,
                              void* d_out, int out_size) {
    const int*   x    = (const int*)d_in[0];
    const float* emb  = (const float*)d_in[1];
    const float* W_ih = (const float*)d_in[2];
    // d_in[3] = W_hh: unused (h0 == 0)
    const float* b_ih = (const float*)d_in[4];
    const float* b_hh = (const float*)d_in[5];
    float* out = (float*)d_out;

    k_lengths<<<Bsz, 256>>>(x);
    k_sort<<<1, Bsz>>>();
    k_gather<<<Bsz, 256>>>(x, emb);
    for (int l = 0; l < NL; l++) {
        int cur = l & 1;
        k_gemm2<<<dim3(24, NPART), 256>>>(W_ih + (size_t)l * 4 * Hsz * Hsz, cur);
        k_act2<<<64, 256>>>(b_ih + (size_t)l * 4 * Hsz, b_hh + (size_t)l * 4 * Hsz,
                            l, cur ^ 1, out);
    }
    k_output<<<dim3(Bsz, 8), 256>>>(out);
}

// round 5
// speedup vs baseline: 1.2003x; 1.2003x over previous
#include <cuda_runtime.h>
#include <cuda_bf16.h>
#include <cstdint>

#define Bsz 128
#define Ssz 512
#define Hsz 1024
#define NL  4
#define NPART 6

// out layout: output [512,128,1024], state_h [4,128,1024], state_c [4,128,1024]
#define OUT_OFF_H ((size_t)512 * 128 * 1024)
#define OUT_OFF_C (OUT_OFF_H + (size_t)4 * 128 * 1024)

// ---------------- scratch (__device__ globals; no allocations allowed) ------
__device__ int      d_len[Bsz];
__device__ int      d_sorted[Bsz];
__device__ int      d_unsort[Bsz];
__device__ int      d_bslast;
__device__ unsigned d_xbh[2][Hsz / 2][Bsz];    // packed bf16x2 hi of x^T: [kpair][r]
__device__ unsigned d_xbl[2][Hsz / 2][Bsz];    // packed bf16x2 lo residual
__device__ float    d_hfin[Bsz][Hsz];          // final top-layer h, row-major [r][hc]
__device__ float    d_G2[NPART][3 * Hsz][Bsz]; // split-K partials: [part][vm][r]

// pack two floats to bf16x2: low half = lo_val (k even), high half = hi_val (k odd)
__device__ __forceinline__ unsigned pack_bf16(float lo_val, float hi_val) {
    unsigned r;
    asm("cvt.rn.bf16x2.f32 %0, %1, %2;" : "=r"(r) : "f"(hi_val), "f"(lo_val));
    return r;
}
__device__ __forceinline__ float bf_lo(unsigned r) { return __uint_as_float(r << 16); }
__device__ __forceinline__ float bf_hi(unsigned r) { return __uint_as_float(r & 0xFFFF0000u); }

// decompose (f0,f1) -> hi pair + lo residual pair
__device__ __forceinline__ void decomp2(float f0, float f1, unsigned& hi, unsigned& lo) {
    hi = pack_bf16(f0, f1);
    lo = pack_bf16(f0 - bf_lo(hi), f1 - bf_hi(hi));
}

// ---------------- kernel 1: lengths[b] = count(x[b,:] > 0) ------------------
__global__ void k_lengths(const int* __restrict__ x) {
    int b = blockIdx.x;
    int t = threadIdx.x;
    int cnt = 0;
    for (int s = t; s < Ssz; s += blockDim.x) cnt += (x[b * Ssz + s] > 0);
    #pragma unroll
    for (int o = 16; o; o >>= 1) cnt += __shfl_down_sync(0xFFFFFFFFu, cnt, o);
    __shared__ int ws[8];
    if ((t & 31) == 0) ws[t >> 5] = cnt;
    __syncthreads();
    if (t == 0) {
        int s = 0;
        for (int w = 0; w < (int)blockDim.x / 32; w++) s += ws[w];
        d_len[b] = s;
    }
}

// ---------------- kernel 2: stable descending argsort (B=128, O(B^2)) -------
__global__ void k_sort() {
    __shared__ int sl[Bsz];
    int i = threadIdx.x;
    sl[i] = d_len[i];
    __syncthreads();
    int li = sl[i];
    int rank = 0, c512 = 0;
    #pragma unroll 8
    for (int j = 0; j < Bsz; j++) {
        int lj = sl[j];
        rank += (lj > li) || (lj == li && j < i);
        c512 += (lj >= Ssz);
    }
    d_unsort[i] = rank;
    d_sorted[rank] = i;
    if (i == 0) d_bslast = c512;
}

// ------- kernel 3: xb{h,l}[0][kp][r] = bf16 decomposition of emb row --------
__global__ void k_gather(const int* __restrict__ x, const float* __restrict__ emb) {
    int r = blockIdx.x;
    int tok = x[d_sorted[r] * Ssz];  // t = 0
    const float2* src = (const float2*)(emb + (size_t)tok * Hsz);
    #pragma unroll
    for (int j = 0; j < 2; j++) {
        int kp = threadIdx.x + j * 256;     // pair index 0..511
        float2 f = src[kp];
        unsigned hi, lo;
        decomp2(f.x, f.y, hi, lo);
        d_xbh[0][kp][r] = hi;
        d_xbl[0][kp][r] = lo;
    }
}

// ---------------- kernel 4: 3x-bf16-split tensor-core GEMM ------------------
// C[vm=3072][r=128] = W_sel[vm][k] * x^T[k][r], k=1024, split-K 6, CTA tile 64x128.
#define ASTR 20    // 64 x 16 fp32 weight tile rows, padded stride
#define BSTR 136   // 8 x 128 uint tile (bf16x2 pairs), padded stride

__device__ __forceinline__ void mma16(float* c, const unsigned* a, const unsigned* b) {
    asm volatile(
        "mma.sync.aligned.m16n8k16.row.col.f32.bf16.bf16.f32 "
        "{%0,%1,%2,%3}, {%4,%5,%6,%7}, {%8,%9}, {%0,%1,%2,%3};"
        : "+f"(c[0]), "+f"(c[1]), "+f"(c[2]), "+f"(c[3])
        : "r"(a[0]), "r"(a[1]), "r"(a[2]), "r"(a[3]), "r"(b[0]), "r"(b[1]));
}
__device__ __forceinline__ void cpa16(unsigned s, const void* g) {
    asm volatile("cp.async.cg.shared.global [%0], [%1], 16;" :: "r"(s), "l"(g));
}

__global__ void __launch_bounds__(256, 2) k_gemm3(const float* __restrict__ W, int cur) {
    __shared__ __align__(16) float    As[2][64 * ASTR];
    __shared__ __align__(16) unsigned Bh[2][8 * BSTR];
    __shared__ __align__(16) unsigned Bl[2][8 * BSTR];

    int tid  = threadIdx.x;
    int vm0  = blockIdx.x * 64;                // 0..3008
    int gate = vm0 >> 10;
    const float* A = W + (size_t)(vm0 + (gate > 0 ? 1024 : 0)) * Hsz;
    const unsigned* XH = &d_xbh[cur][0][0];
    const unsigned* XL = &d_xbl[cur][0][0];

    int part = blockIdx.y;
    int i0 = part * 64 / NPART, i1 = (part + 1) * 64 / NPART;  // BK=16 stages
    int niter = i1 - i0;

    unsigned asb[2], bhb[2], blb[2];
    asb[0] = (unsigned)__cvta_generic_to_shared(&As[0][0]);
    asb[1] = (unsigned)__cvta_generic_to_shared(&As[1][0]);
    bhb[0] = (unsigned)__cvta_generic_to_shared(&Bh[0][0]);
    bhb[1] = (unsigned)__cvta_generic_to_shared(&Bh[1][0]);
    blb[0] = (unsigned)__cvta_generic_to_shared(&Bl[0][0]);
    blb[1] = (unsigned)__cvta_generic_to_shared(&Bl[1][0]);

    // stage loader: A 64x16 fp32 (256 chunks) + Bh 8x128 u32 (256) + Bl (256)
    auto load_stage = [&](int buf, int iter) {
        int kw  = iter * 16;   // float k base
        int kp0 = iter * 8;    // pair base
        {   // A
            int row = tid >> 2, seg = tid & 3;
            cpa16(asb[buf] + (unsigned)(row * ASTR + seg * 4) * 4,
                  A + (size_t)row * Hsz + kw + seg * 4);
        }
        {   // B hi
            int kr = tid >> 5, seg = tid & 31;
            cpa16(bhb[buf] + (unsigned)(kr * BSTR + seg * 4) * 4,
                  XH + (size_t)(kp0 + kr) * Bsz + seg * 4);
        }
        {   // B lo
            int kr = tid >> 5, seg = tid & 31;
            cpa16(blb[buf] + (unsigned)(kr * BSTR + seg * 4) * 4,
                  XL + (size_t)(kp0 + kr) * Bsz + seg * 4);
        }
    };

    int lane = tid & 31, wid = tid >> 5;
    int wm = (wid & 1) * 32;      // warp m offset (gate cols), 2 warps over 64
    int wn = (wid >> 1) * 32;     // warp n offset (batch rows), 4 warps over 128
    int g  = lane >> 2, tg = lane & 3;

    float acc[2][4][4];
    #pragma unroll
    for (int a = 0; a < 2; a++)
        #pragma unroll
        for (int b = 0; b < 4; b++)
            #pragma unroll
            for (int cx = 0; cx < 4; cx++) acc[a][b][cx] = 0.f;

    load_stage(0, i0);
    asm volatile("cp.async.commit_group;" ::: "memory");

    for (int it = 0; it < niter; ++it) {
        if (it + 1 < niter) load_stage((it + 1) & 1, i0 + it + 1);
        asm volatile("cp.async.commit_group;" ::: "memory");
        asm volatile("cp.async.wait_group 1;" ::: "memory");
        __syncthreads();

        const float*    As_ = &As[it & 1][0];
        const unsigned* Bh_ = &Bh[it & 1][0];
        const unsigned* Bl_ = &Bl[it & 1][0];

        // ---- B fragments: direct LDS.32 of pre-packed bf16x2 pairs ----
        unsigned bh[4][2], bl[4][2];
        #pragma unroll
        for (int nf = 0; nf < 4; nf++) {
            int n = wn + nf * 8 + g;
            bh[nf][0] = Bh_[tg * BSTR + n];          // k = 2tg, 2tg+1
            bh[nf][1] = Bh_[(tg + 4) * BSTR + n];    // k = 2tg+8, 2tg+9
            bl[nf][0] = Bl_[tg * BSTR + n];
            bl[nf][1] = Bl_[(tg + 4) * BSTR + n];
        }

        // ---- A fragments: fp32 LDS + bf16 hi/lo decomposition ----
        unsigned ah[2][4], al[2][4];
        #pragma unroll
        for (int mf = 0; mf < 2; mf++) {
            int row0 = wm + mf * 16 + g;
            int row1 = row0 + 8;
            float2 f0 = *(const float2*)&As_[row0 * ASTR + 2 * tg];      // a0: k=2tg,2tg+1
            float2 f1 = *(const float2*)&As_[row1 * ASTR + 2 * tg];      // a1
            float2 f2 = *(const float2*)&As_[row0 * ASTR + 2 * tg + 8];  // a2: k=+8
            float2 f3 = *(const float2*)&As_[row1 * ASTR + 2 * tg + 8];  // a3
            decomp2(f0.x, f0.y, ah[mf][0], al[mf][0]);
            decomp2(f1.x, f1.y, ah[mf][1], al[mf][1]);
            decomp2(f2.x, f2.y, ah[mf][2], al[mf][2]);
            decomp2(f3.x, f3.y, ah[mf][3], al[mf][3]);
        }

        // ---- 3 terms x 8 independent MMAs each ----
        #pragma unroll
        for (int mf = 0; mf < 2; mf++)
            #pragma unroll
            for (int nf = 0; nf < 4; nf++) mma16(acc[mf][nf], ah[mf], bh[nf]);
        #pragma unroll
        for (int mf = 0; mf < 2; mf++)
            #pragma unroll
            for (int nf = 0; nf < 4; nf++) mma16(acc[mf][nf], al[mf], bh[nf]);
        #pragma unroll
        for (int mf = 0; mf < 2; mf++)
            #pragma unroll
            for (int nf = 0; nf < 4; nf++) mma16(acc[mf][nf], ah[mf], bl[nf]);

        __syncthreads();
    }

    // epilogue: write split-K partials, [vm][r]
    float* Gp = &d_G2[part][0][0];
    #pragma unroll
    for (int mf = 0; mf < 2; mf++)
        #pragma unroll
        for (int nf = 0; nf < 4; nf++) {
            int m0 = vm0 + wm + mf * 16 + g;
            int n0 = wn + nf * 8 + tg * 2;
            *(float2*)(Gp + (size_t)m0 * Bsz + n0) =
                make_float2(acc[mf][nf][0], acc[mf][nf][1]);
            *(float2*)(Gp + (size_t)(m0 + 8) * Bsz + n0) =
                make_float2(acc[mf][nf][2], acc[mf][nf][3]);
        }
}

// ---------------- kernel 5: split-K reduce + LSTM activations ---------------
__device__ __forceinline__ float sigmoidf_(float x) { return 1.0f / (1.0f + expf(-x)); }

__global__ void __launch_bounds__(256) k_act3(const float* __restrict__ bih,
                                              const float* __restrict__ bhh,
                                              int l, int nxt, float* __restrict__ out) {
    __shared__ float sh[16][129], sc[16][129];
    int tid = threadIdx.x;
    int hb = blockIdx.x * 16;       // grid = 64 blocks
    int bsl = d_bslast;

    // phase 1: compute hc pairs so we can pack bf16x2 along k for next layer
    #pragma unroll
    for (int w = 0; w < 4; w++) {
        int pidx = w * 256 + tid;             // 0..1023 = 8 pairs x 128 r
        int r  = pidx & 127;
        int pl = pidx >> 7;                    // 0..7 local pair
        int hc0 = hb + 2 * pl;
        float hh2[2], cc2[2];
        #pragma unroll
        for (int e = 0; e < 2; e++) {
            int hc = hc0 + e;
            float gi = 0.f, gg = 0.f, go = 0.f;
            #pragma unroll
            for (int p = 0; p < NPART; p++) {
                gi += d_G2[p][hc][r];
                gg += d_G2[p][Hsz + hc][r];
                go += d_G2[p][2 * Hsz + hc][r];
            }
            gi += bih[hc] + bhh[hc];
            gg += bih[2 * Hsz + hc] + bhh[2 * Hsz + hc];
            go += bih[3 * Hsz + hc] + bhh[3 * Hsz + hc];
            float cc = sigmoidf_(gi) * tanhf(gg);
            float hh = sigmoidf_(go) * tanhf(cc);
            cc2[e] = cc; hh2[e] = hh;
            sh[2 * pl + e][r] = hh;
            sc[2 * pl + e][r] = cc;
        }
        unsigned hi, lo;
        decomp2(hh2[0], hh2[1], hi, lo);
        int kp = (hb >> 1) + pl;
        d_xbh[nxt][kp][r] = hi;               // unmasked h feeds next layer
        d_xbl[nxt][kp][r] = lo;
    }
    __syncthreads();
    // phase 2: masked state writes + final-h row-major copy
    #pragma unroll
    for (int w = 0; w < 8; w++) {
        int idx = w * 256 + tid;
        int r = idx >> 4, hcl = idx & 15;
        float m = (r < bsl) ? 1.f : 0.f;
        size_t o = ((size_t)(l * Bsz + r) << 10) + hb + hcl;
        float hh = sh[hcl][r];
        out[OUT_OFF_H + o] = hh * m;
        out[OUT_OFF_C + o] = sc[hcl][r] * m;
        d_hfin[r][hb + hcl] = hh;              // row-major final h (last layer wins)
    }
}

// ---------------- kernel 6: output[t,b,:] = (t < len[b]) * h_top[b,:] -------
__global__ void k_output(float* __restrict__ out) {
    int b  = blockIdx.x;
    int tb = blockIdx.y * 64;
    int len = d_len[b];
    int rk  = d_unsort[b];
    float4 hv = *(const float4*)&d_hfin[rk][threadIdx.x * 4];
    float4 z  = make_float4(0.f, 0.f, 0.f, 0.f);
    size_t col = (size_t)threadIdx.x * 4;
    #pragma unroll 4
    for (int t = tb; t < tb + 64; t++) {
        float4 v = (t < len) ? hv : z;
        *(float4*)&out[(((size_t)t * Bsz) + b) * Hsz + col] = v;
    }
}

// ---------------- launch -----------------------------------------------------
extern "C" void kernel_launch(void* const* d_in, const int* in_sizes, int n_in,
                              void* d_out, int out_size) {
    const int*   x    = (const int*)d_in[0];
    const float* emb  = (const float*)d_in[1];
    const float* W_ih = (const float*)d_in[2];
    // d_in[3] = W_hh: unused (h0 == 0)
    const float* b_ih = (const float*)d_in[4];
    const float* b_hh = (const float*)d_in[5];
    float* out = (float*)d_out;

    k_lengths<<<Bsz, 256>>>(x);
    k_sort<<<1, Bsz>>>();
    k_gather<<<Bsz, 256>>>(x, emb);
    for (int l = 0; l < NL; l++) {
        int cur = l & 1;
        k_gemm3<<<dim3(48, NPART), 256>>>(W_ih + (size_t)l * 4 * Hsz * Hsz, cur);
        k_act3<<<64, 256>>>(b_ih + (size_t)l * 4 * Hsz, b_hh + (size_t)l * 4 * Hsz,
                            l, cur ^ 1, out);
    }
    k_output<<<dim3(Bsz, 8), 256>>>(out);
}

// round 6
// speedup vs baseline: 1.2286x; 1.0235x over previous
#include <cuda_runtime.h>
#include <cuda_bf16.h>
#include <cstdint>

#define Bsz 128
#define Ssz 512
#define Hsz 1024
#define NL  4
#define NPART 6
#define NST 3

// out layout: output [512,128,1024], state_h [4,128,1024], state_c [4,128,1024]
#define OUT_OFF_H ((size_t)512 * 128 * 1024)
#define OUT_OFF_C (OUT_OFF_H + (size_t)4 * 128 * 1024)

// ---------------- scratch (__device__ globals; no allocations allowed) ------
__device__ int      d_len[Bsz];
__device__ int      d_sorted[Bsz];
__device__ int      d_unsort[Bsz];
__device__ int      d_bslast;
__device__ unsigned d_xbh[2][Hsz / 2][Bsz];    // packed bf16x2 hi of x^T: [kpair][r]
__device__ unsigned d_xbl[2][Hsz / 2][Bsz];    // packed bf16x2 lo residual
__device__ float    d_hfin[Bsz][Hsz];          // final top-layer h, row-major [r][hc]
__device__ float    d_G2[NPART][3 * Hsz][Bsz]; // split-K partials: [part][vm][r]

// pack two floats to bf16x2: low half = lo_val (k even), high half = hi_val (k odd)
__device__ __forceinline__ unsigned pack_bf16(float lo_val, float hi_val) {
    unsigned r;
    asm("cvt.rn.bf16x2.f32 %0, %1, %2;" : "=r"(r) : "f"(hi_val), "f"(lo_val));
    return r;
}
__device__ __forceinline__ float bf_lo(unsigned r) { return __uint_as_float(r << 16); }
__device__ __forceinline__ float bf_hi(unsigned r) { return __uint_as_float(r & 0xFFFF0000u); }

// decompose (f0,f1) -> hi pair + lo residual pair
__device__ __forceinline__ void decomp2(float f0, float f1, unsigned& hi, unsigned& lo) {
    hi = pack_bf16(f0, f1);
    lo = pack_bf16(f0 - bf_lo(hi), f1 - bf_hi(hi));
}

// ---------------- kernel 1: lengths[b] = count(x[b,:] > 0) ------------------
__global__ void k_lengths(const int* __restrict__ x) {
    int b = blockIdx.x;
    int t = threadIdx.x;
    int cnt = 0;
    for (int s = t; s < Ssz; s += blockDim.x) cnt += (x[b * Ssz + s] > 0);
    #pragma unroll
    for (int o = 16; o; o >>= 1) cnt += __shfl_down_sync(0xFFFFFFFFu, cnt, o);
    __shared__ int ws[8];
    if ((t & 31) == 0) ws[t >> 5] = cnt;
    __syncthreads();
    if (t == 0) {
        int s = 0;
        for (int w = 0; w < (int)blockDim.x / 32; w++) s += ws[w];
        d_len[b] = s;
    }
}

// ---------------- kernel 2: stable descending argsort (B=128, O(B^2)) -------
__global__ void k_sort() {
    __shared__ int sl[Bsz];
    int i = threadIdx.x;
    sl[i] = d_len[i];
    __syncthreads();
    int li = sl[i];
    int rank = 0, c512 = 0;
    #pragma unroll 8
    for (int j = 0; j < Bsz; j++) {
        int lj = sl[j];
        rank += (lj > li) || (lj == li && j < i);
        c512 += (lj >= Ssz);
    }
    d_unsort[i] = rank;
    d_sorted[rank] = i;
    if (i == 0) d_bslast = c512;
}

// ------- kernel 3: xb{h,l}[0][kp][r] = bf16 decomposition of emb row --------
__global__ void k_gather(const int* __restrict__ x, const float* __restrict__ emb) {
    int r = blockIdx.x;
    int tok = x[d_sorted[r] * Ssz];  // t = 0
    const float2* src = (const float2*)(emb + (size_t)tok * Hsz);
    #pragma unroll
    for (int j = 0; j < 2; j++) {
        int kp = threadIdx.x + j * 256;     // pair index 0..511
        float2 f = src[kp];
        unsigned hi, lo;
        decomp2(f.x, f.y, hi, lo);
        d_xbh[0][kp][r] = hi;
        d_xbl[0][kp][r] = lo;
    }
}

// ---------------- kernel 4: 3x-bf16-split tensor-core GEMM ------------------
// C[vm=3072][r=128] = W_sel[vm][k] * x^T[k][r], k=1024, split-K 6, CTA tile 64x128.
// 3-stage circular cp.async pipeline, ONE __syncthreads per stage.
#define ASTR 20    // 64 x 16 fp32 weight tile rows, padded stride
#define BSTR 136   // 8 x 128 uint tile (bf16x2 pairs), padded stride

__device__ __forceinline__ void mma16(float* c, const unsigned* a, const unsigned* b) {
    asm volatile(
        "mma.sync.aligned.m16n8k16.row.col.f32.bf16.bf16.f32 "
        "{%0,%1,%2,%3}, {%4,%5,%6,%7}, {%8,%9}, {%0,%1,%2,%3};"
        : "+f"(c[0]), "+f"(c[1]), "+f"(c[2]), "+f"(c[3])
        : "r"(a[0]), "r"(a[1]), "r"(a[2]), "r"(a[3]), "r"(b[0]), "r"(b[1]));
}
__device__ __forceinline__ void cpa16(unsigned s, const void* g) {
    asm volatile("cp.async.cg.shared.global [%0], [%1], 16;" :: "r"(s), "l"(g));
}

__global__ void __launch_bounds__(256, 2) k_gemm3(const float* __restrict__ W, int cur) {
    __shared__ __align__(16) float    As[NST][64 * ASTR];
    __shared__ __align__(16) unsigned Bh[NST][8 * BSTR];
    __shared__ __align__(16) unsigned Bl[NST][8 * BSTR];

    int tid  = threadIdx.x;
    int vm0  = blockIdx.x * 64;                // 0..3008
    int gate = vm0 >> 10;
    const float* A = W + (size_t)(vm0 + (gate > 0 ? 1024 : 0)) * Hsz;
    const unsigned* XH = &d_xbh[cur][0][0];
    const unsigned* XL = &d_xbl[cur][0][0];

    int part = blockIdx.y;
    int i0 = part * 64 / NPART, i1 = (part + 1) * 64 / NPART;  // BK=16 stages
    int niter = i1 - i0;

    unsigned asb[NST], bhb[NST], blb[NST];
    #pragma unroll
    for (int s = 0; s < NST; s++) {
        asb[s] = (unsigned)__cvta_generic_to_shared(&As[s][0]);
        bhb[s] = (unsigned)__cvta_generic_to_shared(&Bh[s][0]);
        blb[s] = (unsigned)__cvta_generic_to_shared(&Bl[s][0]);
    }

    // per-thread precomputed loader offsets
    int a_row = tid >> 2, a_seg = tid & 3;
    int b_kr  = tid >> 5, b_seg = tid & 31;
    unsigned a_soff = (unsigned)(a_row * ASTR + a_seg * 4) * 4;
    unsigned b_soff = (unsigned)(b_kr * BSTR + b_seg * 4) * 4;

    auto load_stage = [&](int buf, int iter) {
        int kw  = iter * 16;   // float k base
        int kp0 = iter * 8;    // pair base
        cpa16(asb[buf] + a_soff, A + (size_t)a_row * Hsz + kw + a_seg * 4);
        cpa16(bhb[buf] + b_soff, XH + (size_t)(kp0 + b_kr) * Bsz + b_seg * 4);
        cpa16(blb[buf] + b_soff, XL + (size_t)(kp0 + b_kr) * Bsz + b_seg * 4);
    };

    int lane = tid & 31, wid = tid >> 5;
    int wm = (wid & 1) * 32;      // warp m offset (gate cols), 2 warps over 64
    int wn = (wid >> 1) * 32;     // warp n offset (batch rows), 4 warps over 128
    int g  = lane >> 2, tg = lane & 3;

    float acc[2][4][4];
    #pragma unroll
    for (int a = 0; a < 2; a++)
        #pragma unroll
        for (int b = 0; b < 4; b++)
            #pragma unroll
            for (int cx = 0; cx < 4; cx++) acc[a][b][cx] = 0.f;

    // prologue: stages 0 and 1 in flight
    load_stage(0, i0);
    asm volatile("cp.async.commit_group;" ::: "memory");
    if (niter > 1) load_stage(1, i0 + 1);
    asm volatile("cp.async.commit_group;" ::: "memory");

    for (int it = 0; it < niter; ++it) {
        asm volatile("cp.async.wait_group 1;" ::: "memory");
        __syncthreads();

        // prefetch stage it+2 into the buffer consumed at iteration it-1
        if (it + 2 < niter) load_stage((it + 2) % NST, i0 + it + 2);
        asm volatile("cp.async.commit_group;" ::: "memory");

        int buf = it % NST;
        const float*    As_ = &As[buf][0];
        const unsigned* Bh_ = &Bh[buf][0];
        const unsigned* Bl_ = &Bl[buf][0];

        // ---- B fragments: direct LDS.32 of pre-packed bf16x2 pairs ----
        unsigned bh[4][2], bl[4][2];
        #pragma unroll
        for (int nf = 0; nf < 4; nf++) {
            int n = wn + nf * 8 + g;
            bh[nf][0] = Bh_[tg * BSTR + n];          // k = 2tg, 2tg+1
            bh[nf][1] = Bh_[(tg + 4) * BSTR + n];    // k = 2tg+8, 2tg+9
            bl[nf][0] = Bl_[tg * BSTR + n];
            bl[nf][1] = Bl_[(tg + 4) * BSTR + n];
        }

        // ---- A fragments: fp32 LDS + bf16 hi/lo decomposition ----
        unsigned ah[2][4], al[2][4];
        #pragma unroll
        for (int mf = 0; mf < 2; mf++) {
            int row0 = wm + mf * 16 + g;
            int row1 = row0 + 8;
            float2 f0 = *(const float2*)&As_[row0 * ASTR + 2 * tg];      // k=2tg,2tg+1
            float2 f1 = *(const float2*)&As_[row1 * ASTR + 2 * tg];
            float2 f2 = *(const float2*)&As_[row0 * ASTR + 2 * tg + 8];  // k=+8
            float2 f3 = *(const float2*)&As_[row1 * ASTR + 2 * tg + 8];
            decomp2(f0.x, f0.y, ah[mf][0], al[mf][0]);
            decomp2(f1.x, f1.y, ah[mf][1], al[mf][1]);
            decomp2(f2.x, f2.y, ah[mf][2], al[mf][2]);
            decomp2(f3.x, f3.y, ah[mf][3], al[mf][3]);
        }

        // ---- 3 terms x 8 independent MMAs each ----
        #pragma unroll
        for (int mf = 0; mf < 2; mf++)
            #pragma unroll
            for (int nf = 0; nf < 4; nf++) mma16(acc[mf][nf], ah[mf], bh[nf]);
        #pragma unroll
        for (int mf = 0; mf < 2; mf++)
            #pragma unroll
            for (int nf = 0; nf < 4; nf++) mma16(acc[mf][nf], al[mf], bh[nf]);
        #pragma unroll
        for (int mf = 0; mf < 2; mf++)
            #pragma unroll
            for (int nf = 0; nf < 4; nf++) mma16(acc[mf][nf], ah[mf], bl[nf]);
    }

    // epilogue: write split-K partials, [vm][r]
    float* Gp = &d_G2[part][0][0];
    #pragma unroll
    for (int mf = 0; mf < 2; mf++)
        #pragma unroll
        for (int nf = 0; nf < 4; nf++) {
            int m0 = vm0 + wm + mf * 16 + g;
            int n0 = wn + nf * 8 + tg * 2;
            *(float2*)(Gp + (size_t)m0 * Bsz + n0) =
                make_float2(acc[mf][nf][0], acc[mf][nf][1]);
            *(float2*)(Gp + (size_t)(m0 + 8) * Bsz + n0) =
                make_float2(acc[mf][nf][2], acc[mf][nf][3]);
        }
}

// ---------------- kernel 5: split-K reduce + LSTM activations ---------------
__device__ __forceinline__ float sigmoidf_(float x) { return 1.0f / (1.0f + expf(-x)); }

__global__ void __launch_bounds__(256) k_act3(const float* __restrict__ bih,
                                              const float* __restrict__ bhh,
                                              int l, int nxt, float* __restrict__ out) {
    __shared__ float sh[16][129], sc[16][129];
    int tid = threadIdx.x;
    int hb = blockIdx.x * 16;       // grid = 64 blocks
    int bsl = d_bslast;

    // phase 1: compute hc pairs so we can pack bf16x2 along k for next layer
    #pragma unroll
    for (int w = 0; w < 4; w++) {
        int pidx = w * 256 + tid;             // 0..1023 = 8 pairs x 128 r
        int r  = pidx & 127;
        int pl = pidx >> 7;                    // 0..7 local pair
        int hc0 = hb + 2 * pl;
        float hh2[2], cc2[2];
        #pragma unroll
        for (int e = 0; e < 2; e++) {
            int hc = hc0 + e;
            float gi = 0.f, gg = 0.f, go = 0.f;
            #pragma unroll
            for (int p = 0; p < NPART; p++) {
                gi += d_G2[p][hc][r];
                gg += d_G2[p][Hsz + hc][r];
                go += d_G2[p][2 * Hsz + hc][r];
            }
            gi += bih[hc] + bhh[hc];
            gg += bih[2 * Hsz + hc] + bhh[2 * Hsz + hc];
            go += bih[3 * Hsz + hc] + bhh[3 * Hsz + hc];
            float cc = sigmoidf_(gi) * tanhf(gg);
            float hh = sigmoidf_(go) * tanhf(cc);
            cc2[e] = cc; hh2[e] = hh;
            sh[2 * pl + e][r] = hh;
            sc[2 * pl + e][r] = cc;
        }
        unsigned hi, lo;
        decomp2(hh2[0], hh2[1], hi, lo);
        int kp = (hb >> 1) + pl;
        d_xbh[nxt][kp][r] = hi;               // unmasked h feeds next layer
        d_xbl[nxt][kp][r] = lo;
    }
    __syncthreads();
    // phase 2: masked state writes + final-h row-major copy
    #pragma unroll
    for (int w = 0; w < 8; w++) {
        int idx = w * 256 + tid;
        int r = idx >> 4, hcl = idx & 15;
        float m = (r < bsl) ? 1.f : 0.f;
        size_t o = ((size_t)(l * Bsz + r) << 10) + hb + hcl;
        float hh = sh[hcl][r];
        out[OUT_OFF_H + o] = hh * m;
        out[OUT_OFF_C + o] = sc[hcl][r] * m;
        d_hfin[r][hb + hcl] = hh;              // row-major final h (last layer wins)
    }
}

// ---------------- kernel 6: output[t,b,:] = (t < len[b]) * h_top[b,:] -------
__global__ void k_output(float* __restrict__ out) {
    int b  = blockIdx.x;
    int tb = blockIdx.y * 64;
    int len = d_len[b];
    int rk  = d_unsort[b];
    float4 hv = *(const float4*)&d_hfin[rk][threadIdx.x * 4];
    float4 z  = make_float4(0.f, 0.f, 0.f, 0.f);
    size_t col = (size_t)threadIdx.x * 4;
    #pragma unroll 4
    for (int t = tb; t < tb + 64; t++) {
        float4 v = (t < len) ? hv : z;
        *(float4*)&out[(((size_t)t * Bsz) + b) * Hsz + col] = v;
    }
}

// ---------------- launch -----------------------------------------------------
extern "C" void kernel_launch(void* const* d_in, const int* in_sizes, int n_in,
                              void* d_out, int out_size) {
    const int*   x    = (const int*)d_in[0];
    const float* emb  = (const float*)d_in[1];
    const float* W_ih = (const float*)d_in[2];
    // d_in[3] = W_hh: unused (h0 == 0)
    const float* b_ih = (const float*)d_in[4];
    const float* b_hh = (const float*)d_in[5];
    float* out = (float*)d_out;

    k_lengths<<<Bsz, 256>>>(x);
    k_sort<<<1, Bsz>>>();
    k_gather<<<Bsz, 256>>>(x, emb);
    for (int l = 0; l < NL; l++) {
        int cur = l & 1;
        k_gemm3<<<dim3(48, NPART), 256>>>(W_ih + (size_t)l * 4 * Hsz * Hsz, cur);
        k_act3<<<64, 256>>>(b_ih + (size_t)l * 4 * Hsz, b_hh + (size_t)l * 4 * Hsz,
                            l, cur ^ 1, out);
    }
    k_output<<<dim3(Bsz, 8), 256>>>(out);
}

// round 7
// speedup vs baseline: 1.2498x; 1.0173x over previous
#include <cuda_runtime.h>
#include <cuda_bf16.h>
#include <cstdint>

#define Bsz 128
#define Ssz 512
#define Hsz 1024
#define NL  4
#define NPART 6
#define NST 3

// out layout: output [512,128,1024], state_h [4,128,1024], state_c [4,128,1024]
#define OUT_OFF_H ((size_t)512 * 128 * 1024)
#define OUT_OFF_C (OUT_OFF_H + (size_t)4 * 128 * 1024)

// ---------------- scratch (__device__ globals; no allocations allowed) ------
__device__ int      d_len[Bsz];
__device__ int      d_sorted[Bsz];
__device__ int      d_unsort[Bsz];
__device__ int      d_bslast;
__device__ unsigned d_xbh[2][Hsz / 2][Bsz];    // packed bf16x2 hi of x^T: [kpair][r]
__device__ unsigned d_xbl[2][Hsz / 2][Bsz];    // packed bf16x2 lo residual
__device__ float    d_hfin[Bsz][Hsz];          // final top-layer h, row-major [r][hc]
__device__ float    d_G2[NPART][3 * Hsz][Bsz]; // split-K partials: [part][vm][r]

// pack two floats to bf16x2: low half = lo_val (k even), high half = hi_val (k odd)
__device__ __forceinline__ unsigned pack_bf16(float lo_val, float hi_val) {
    unsigned r;
    asm("cvt.rn.bf16x2.f32 %0, %1, %2;" : "=r"(r) : "f"(hi_val), "f"(lo_val));
    return r;
}
__device__ __forceinline__ float bf_lo(unsigned r) { return __uint_as_float(r << 16); }
__device__ __forceinline__ float bf_hi(unsigned r) { return __uint_as_float(r & 0xFFFF0000u); }

// decompose (f0,f1) -> hi pair + lo residual pair
__device__ __forceinline__ void decomp2(float f0, float f1, unsigned& hi, unsigned& lo) {
    hi = pack_bf16(f0, f1);
    lo = pack_bf16(f0 - bf_lo(hi), f1 - bf_hi(hi));
}

// ---------------- kernel 1: lengths[b] = count(x[b,:] > 0) ------------------
__global__ void k_lengths(const int* __restrict__ x) {
    int b = blockIdx.x;
    int t = threadIdx.x;
    int cnt = 0;
    for (int s = t; s < Ssz; s += blockDim.x) cnt += (x[b * Ssz + s] > 0);
    #pragma unroll
    for (int o = 16; o; o >>= 1) cnt += __shfl_down_sync(0xFFFFFFFFu, cnt, o);
    __shared__ int ws[8];
    if ((t & 31) == 0) ws[t >> 5] = cnt;
    __syncthreads();
    if (t == 0) {
        int s = 0;
        for (int w = 0; w < (int)blockDim.x / 32; w++) s += ws[w];
        d_len[b] = s;
    }
}

// ---------------- kernel 2: stable descending argsort (B=128, O(B^2)) -------
__global__ void k_sort() {
    __shared__ int sl[Bsz];
    int i = threadIdx.x;
    sl[i] = d_len[i];
    __syncthreads();
    int li = sl[i];
    int rank = 0, c512 = 0;
    #pragma unroll 8
    for (int j = 0; j < Bsz; j++) {
        int lj = sl[j];
        rank += (lj > li) || (lj == li && j < i);
        c512 += (lj >= Ssz);
    }
    d_unsort[i] = rank;
    d_sorted[rank] = i;
    if (i == 0) d_bslast = c512;
}

// ------- kernel 3: xb{h,l}[0][kp][r] = bf16 decomposition of emb row --------
__global__ void k_gather(const int* __restrict__ x, const float* __restrict__ emb) {
    int r = blockIdx.x;
    int tok = x[d_sorted[r] * Ssz];  // t = 0
    const float2* src = (const float2*)(emb + (size_t)tok * Hsz);
    #pragma unroll
    for (int j = 0; j < 2; j++) {
        int kp = threadIdx.x + j * 256;     // pair index 0..511
        float2 f = src[kp];
        unsigned hi, lo;
        decomp2(f.x, f.y, hi, lo);
        d_xbh[0][kp][r] = hi;
        d_xbl[0][kp][r] = lo;
    }
}

// ---------------- kernel 4: 3x-bf16-split tensor-core GEMM ------------------
// C[vm=3072][r=128] = W_sel[vm][k] * x^T[k][r], k=1024, split-K 6, CTA tile 64x128.
// Warp tile: 16m x 64n (mf=1, nf=8) -> half the redundant A decomposition.
#define ASTR 20    // 64 x 16 fp32 weight tile rows, padded stride
#define BSTR 136   // 8 x 128 uint tile (bf16x2 pairs), padded stride

__device__ __forceinline__ void mma16(float* c, const unsigned* a, const unsigned* b) {
    asm volatile(
        "mma.sync.aligned.m16n8k16.row.col.f32.bf16.bf16.f32 "
        "{%0,%1,%2,%3}, {%4,%5,%6,%7}, {%8,%9}, {%0,%1,%2,%3};"
        : "+f"(c[0]), "+f"(c[1]), "+f"(c[2]), "+f"(c[3])
        : "r"(a[0]), "r"(a[1]), "r"(a[2]), "r"(a[3]), "r"(b[0]), "r"(b[1]));
}
__device__ __forceinline__ void cpa16(unsigned s, const void* g) {
    asm volatile("cp.async.cg.shared.global [%0], [%1], 16;" :: "r"(s), "l"(g));
}

__global__ void __launch_bounds__(256, 2) k_gemm3(const float* __restrict__ W, int cur) {
    __shared__ __align__(16) float    As[NST][64 * ASTR];
    __shared__ __align__(16) unsigned Bh[NST][8 * BSTR];
    __shared__ __align__(16) unsigned Bl[NST][8 * BSTR];

    int tid  = threadIdx.x;
    int vm0  = blockIdx.x * 64;                // 0..3008
    int gate = vm0 >> 10;
    const float* A = W + (size_t)(vm0 + (gate > 0 ? 1024 : 0)) * Hsz;
    const unsigned* XH = &d_xbh[cur][0][0];
    const unsigned* XL = &d_xbl[cur][0][0];

    int part = blockIdx.y;
    int i0 = part * 64 / NPART, i1 = (part + 1) * 64 / NPART;  // BK=16 stages
    int niter = i1 - i0;

    unsigned asb[NST], bhb[NST], blb[NST];
    #pragma unroll
    for (int s = 0; s < NST; s++) {
        asb[s] = (unsigned)__cvta_generic_to_shared(&As[s][0]);
        bhb[s] = (unsigned)__cvta_generic_to_shared(&Bh[s][0]);
        blb[s] = (unsigned)__cvta_generic_to_shared(&Bl[s][0]);
    }

    // per-thread precomputed loader offsets
    int a_row = tid >> 2, a_seg = tid & 3;
    int b_kr  = tid >> 5, b_seg = tid & 31;
    unsigned a_soff = (unsigned)(a_row * ASTR + a_seg * 4) * 4;
    unsigned b_soff = (unsigned)(b_kr * BSTR + b_seg * 4) * 4;

    auto load_stage = [&](int buf, int iter) {
        int kw  = iter * 16;   // float k base
        int kp0 = iter * 8;    // pair base
        cpa16(asb[buf] + a_soff, A + (size_t)a_row * Hsz + kw + a_seg * 4);
        cpa16(bhb[buf] + b_soff, XH + (size_t)(kp0 + b_kr) * Bsz + b_seg * 4);
        cpa16(blb[buf] + b_soff, XL + (size_t)(kp0 + b_kr) * Bsz + b_seg * 4);
    };

    int lane = tid & 31, wid = tid >> 5;
    int wm = (wid & 3) * 16;      // warp m offset: 4 warps over 64 gate cols
    int wn = (wid >> 2) * 64;     // warp n offset: 2 warps over 128 batch rows
    int g  = lane >> 2, tg = lane & 3;

    float acc[8][4];
    #pragma unroll
    for (int b = 0; b < 8; b++)
        #pragma unroll
        for (int cx = 0; cx < 4; cx++) acc[b][cx] = 0.f;

    // prologue: stages 0 and 1 in flight
    load_stage(0, i0);
    asm volatile("cp.async.commit_group;" ::: "memory");
    if (niter > 1) load_stage(1, i0 + 1);
    asm volatile("cp.async.commit_group;" ::: "memory");

    for (int it = 0; it < niter; ++it) {
        asm volatile("cp.async.wait_group 1;" ::: "memory");
        __syncthreads();

        // prefetch stage it+2 into the buffer consumed at iteration it-1
        if (it + 2 < niter) load_stage((it + 2) % NST, i0 + it + 2);
        asm volatile("cp.async.commit_group;" ::: "memory");

        int buf = it % NST;
        const float*    As_ = &As[buf][0];
        const unsigned* Bh_ = &Bh[buf][0];
        const unsigned* Bl_ = &Bl[buf][0];

        // ---- A fragments first (decomp on FMA pipe overlaps B LDS latency) --
        unsigned ah[4], al[4];
        {
            int row0 = wm + g;
            int row1 = row0 + 8;
            float2 f0 = *(const float2*)&As_[row0 * ASTR + 2 * tg];      // k=2tg,2tg+1
            float2 f1 = *(const float2*)&As_[row1 * ASTR + 2 * tg];
            float2 f2 = *(const float2*)&As_[row0 * ASTR + 2 * tg + 8];  // k=+8
            float2 f3 = *(const float2*)&As_[row1 * ASTR + 2 * tg + 8];
            decomp2(f0.x, f0.y, ah[0], al[0]);
            decomp2(f1.x, f1.y, ah[1], al[1]);
            decomp2(f2.x, f2.y, ah[2], al[2]);
            decomp2(f3.x, f3.y, ah[3], al[3]);
        }

        // ---- B fragments: direct LDS.32 of pre-packed bf16x2 pairs ----
        unsigned bh[8][2], bl[8][2];
        #pragma unroll
        for (int nf = 0; nf < 8; nf++) {
            int n = wn + nf * 8 + g;
            bh[nf][0] = Bh_[tg * BSTR + n];          // k = 2tg, 2tg+1
            bh[nf][1] = Bh_[(tg + 4) * BSTR + n];    // k = 2tg+8, 2tg+9
            bl[nf][0] = Bl_[tg * BSTR + n];
            bl[nf][1] = Bl_[(tg + 4) * BSTR + n];
        }

        // ---- 3 terms x 8 independent MMAs each ----
        #pragma unroll
        for (int nf = 0; nf < 8; nf++) mma16(acc[nf], ah, bh[nf]);
        #pragma unroll
        for (int nf = 0; nf < 8; nf++) mma16(acc[nf], al, bh[nf]);
        #pragma unroll
        for (int nf = 0; nf < 8; nf++) mma16(acc[nf], ah, bl[nf]);
    }

    // epilogue: write split-K partials, [vm][r]
    float* Gp = &d_G2[part][0][0];
    int m0 = vm0 + wm + g;
    #pragma unroll
    for (int nf = 0; nf < 8; nf++) {
        int n0 = wn + nf * 8 + tg * 2;
        *(float2*)(Gp + (size_t)m0 * Bsz + n0) =
            make_float2(acc[nf][0], acc[nf][1]);
        *(float2*)(Gp + (size_t)(m0 + 8) * Bsz + n0) =
            make_float2(acc[nf][2], acc[nf][3]);
    }
}

// ---------------- kernel 5: split-K reduce + LSTM activations ---------------
__device__ __forceinline__ float sigmoidf_(float x) { return 1.0f / (1.0f + expf(-x)); }

__global__ void __launch_bounds__(256) k_act3(const float* __restrict__ bih,
                                              const float* __restrict__ bhh,
                                              int l, int nxt, float* __restrict__ out) {
    __shared__ float sh[16][129], sc[16][129];
    int tid = threadIdx.x;
    int hb = blockIdx.x * 16;       // grid = 64 blocks
    int bsl = d_bslast;

    // phase 1: compute hc pairs so we can pack bf16x2 along k for next layer
    #pragma unroll
    for (int w = 0; w < 4; w++) {
        int pidx = w * 256 + tid;             // 0..1023 = 8 pairs x 128 r
        int r  = pidx & 127;
        int pl = pidx >> 7;                    // 0..7 local pair
        int hc0 = hb + 2 * pl;
        float hh2[2], cc2[2];
        #pragma unroll
        for (int e = 0; e < 2; e++) {
            int hc = hc0 + e;
            float gi = 0.f, gg = 0.f, go = 0.f;
            #pragma unroll
            for (int p = 0; p < NPART; p++) {
                gi += d_G2[p][hc][r];
                gg += d_G2[p][Hsz + hc][r];
                go += d_G2[p][2 * Hsz + hc][r];
            }
            gi += bih[hc] + bhh[hc];
            gg += bih[2 * Hsz + hc] + bhh[2 * Hsz + hc];
            go += bih[3 * Hsz + hc] + bhh[3 * Hsz + hc];
            float cc = sigmoidf_(gi) * tanhf(gg);
            float hh = sigmoidf_(go) * tanhf(cc);
            cc2[e] = cc; hh2[e] = hh;
            sh[2 * pl + e][r] = hh;
            sc[2 * pl + e][r] = cc;
        }
        unsigned hi, lo;
        decomp2(hh2[0], hh2[1], hi, lo);
        int kp = (hb >> 1) + pl;
        d_xbh[nxt][kp][r] = hi;               // unmasked h feeds next layer
        d_xbl[nxt][kp][r] = lo;
    }
    __syncthreads();
    // phase 2: masked state writes + final-h row-major copy
    #pragma unroll
    for (int w = 0; w < 8; w++) {
        int idx = w * 256 + tid;
        int r = idx >> 4, hcl = idx & 15;
        float m = (r < bsl) ? 1.f : 0.f;
        size_t o = ((size_t)(l * Bsz + r) << 10) + hb + hcl;
        float hh = sh[hcl][r];
        out[OUT_OFF_H + o] = hh * m;
        out[OUT_OFF_C + o] = sc[hcl][r] * m;
        d_hfin[r][hb + hcl] = hh;              // row-major final h (last layer wins)
    }
}

// ---------------- kernel 6: output[t,b,:] = (t < len[b]) * h_top[b,:] -------
__global__ void k_output(float* __restrict__ out) {
    int b  = blockIdx.x;
    int tb = blockIdx.y * 64;
    int len = d_len[b];
    int rk  = d_unsort[b];
    float4 hv = *(const float4*)&d_hfin[rk][threadIdx.x * 4];
    float4 z  = make_float4(0.f, 0.f, 0.f, 0.f);
    size_t col = (size_t)threadIdx.x * 4;
    #pragma unroll 4
    for (int t = tb; t < tb + 64; t++) {
        float4 v = (t < len) ? hv : z;
        // streaming store: 268 MB write-once stream, avoid L2 write-allocate thrash
        __stcs((float4*)&out[(((size_t)t * Bsz) + b) * Hsz + col], v);
    }
}

// ---------------- launch -----------------------------------------------------
extern "C" void kernel_launch(void* const* d_in, const int* in_sizes, int n_in,
                              void* d_out, int out_size) {
    const int*   x    = (const int*)d_in[0];
    const float* emb  = (const float*)d_in[1];
    const float* W_ih = (const float*)d_in[2];
    // d_in[3] = W_hh: unused (h0 == 0)
    const float* b_ih = (const float*)d_in[4];
    const float* b_hh = (const float*)d_in[5];
    float* out = (float*)d_out;

    k_lengths<<<Bsz, 256>>>(x);
    k_sort<<<1, Bsz>>>();
    k_gather<<<Bsz, 256>>>(x, emb);
    for (int l = 0; l < NL; l++) {
        int cur = l & 1;
        k_gemm3<<<dim3(48, NPART), 256>>>(W_ih + (size_t)l * 4 * Hsz * Hsz, cur);
        k_act3<<<64, 256>>>(b_ih + (size_t)l * 4 * Hsz, b_hh + (size_t)l * 4 * Hsz,
                            l, cur ^ 1, out);
    }
    k_output<<<dim3(Bsz, 8), 256>>>(out);
}